// round 14
// baseline (speedup 1.0000x reference)
#include <cuda_runtime.h>
#include <math.h>

#define B_ 8
#define NPTS 2048
#define KNB 10
#define KSEL 16
#define EPSV 1e-5f
#define MTOT (B_ * NPTS)

// ---------------- scratch (no allocation allowed) ----------------
__device__ float  d_x1[MTOT * 64];
__device__ float  d_x2[MTOT * 64];
__device__ float  d_x3[MTOT * 128];
__device__ float  d_x4[MTOT * 256];
__device__ float  d_yz[MTOT * 512];
__device__ float  d_dist[(size_t)MTOT * NPTS];   // per-batch slices used
__device__ int    d_idxbuf[MTOT * KNB];
__device__ int    d_cand[MTOT * KSEL];
__device__ double d_norm[MTOT];
__device__ float  d_normf[MTOT];
__device__ float  d_wp[512 * 128];
__device__ float  d_part[B_ * 16 * 512];
__device__ float  d_gmax[B_ * 512];

// ---------------- helpers ----------------
__device__ __forceinline__ void ins4(float v[4], int id[4], float d, int m) {
    if (d > v[3]) {
        float cv = d; int ci = m;
#pragma unroll
        for (int p = 0; p < 4; ++p) {
            if (cv > v[p]) {
                float t = v[p]; v[p] = cv; cv = t;
                int u = id[p]; id[p] = ci; ci = u;
            }
        }
    }
}

// ---------------- point norms: one warp per point; fp64 (rerank) + fp32 (pass-1) ----------------
template <int C>
__global__ void compute_norms(const float* __restrict__ x, double* __restrict__ nrm,
                              float* __restrict__ nrmf) {
    const unsigned FULL = 0xffffffffu;
    const int gw = (blockIdx.x * 256 + threadIdx.x) >> 5;
    const int lane = threadIdx.x & 31;
    if (gw >= MTOT) return;
    const float* p = x + (size_t)gw * C;
    double s = 0.0;
#pragma unroll
    for (int c = lane; c < C; c += 32) { double v = (double)p[c]; s += v * v; }
#pragma unroll
    for (int off = 16; off; off >>= 1) s += __shfl_down_sync(FULL, s, off);
    if (lane == 0) { nrm[gw] = s; nrmf[gw] = (float)s; }
}

// ---------------- 128x128 tile GEMM, 8x8 microtile, 256 thr, double-buffered k-loop ----------
// DIST=true : Y[(bz*NPTS + n)*NPTS + m] = 2*<x_n, x_m> - ||x_m||^2
// DIST=false: Y[n*N + m] = <X_n, W_m>
template <int K, bool DIST>
__global__ void __launch_bounds__(256)
gemm128(const float* __restrict__ A, const float* __restrict__ Bw,
        const float* __restrict__ nf, float* __restrict__ Y, int N) {
    __shared__ float sA[16][132];
    __shared__ float sB[16][132];
    const int bz = blockIdx.z;
    const float* Ab = A + (DIST ? (size_t)bz * NPTS * K : (size_t)0);
    const float* Bb = DIST ? Ab : Bw;
    const int rt0 = blockIdx.y * 128;   // output rows (n)
    const int ct0 = blockIdx.x * 128;   // output cols (m)
    const int tid = threadIdx.x;
    const int tx = tid & 15, ty = tid >> 4;

    float acc[8][8] = {};
    constexpr int NT = (K + 15) / 16;

    if (NT == 1) {
        // single k-tile path (K=5)
        for (int i = tid; i < 2048; i += 256) {
            int r = i >> 4, k = i & 15;
            sA[k][r] = (k < K) ? Ab[(size_t)(rt0 + r) * K + k] : 0.f;
            sB[k][r] = (k < K) ? Bb[(size_t)(ct0 + r) * K + k] : 0.f;
        }
        __syncthreads();
#pragma unroll
        for (int kk = 0; kk < 16; ++kk) {
            float a[8], bb[8];
            *(float4*)&a[0]  = *(const float4*)&sA[kk][ty * 8];
            *(float4*)&a[4]  = *(const float4*)&sA[kk][ty * 8 + 4];
            *(float4*)&bb[0] = *(const float4*)&sB[kk][tx * 8];
            *(float4*)&bb[4] = *(const float4*)&sB[kk][tx * 8 + 4];
#pragma unroll
            for (int i2 = 0; i2 < 8; ++i2)
#pragma unroll
                for (int j2 = 0; j2 < 8; ++j2)
                    acc[i2][j2] += a[i2] * bb[j2];
        }
        __syncthreads();
    } else {
        // double-buffered: prefetch tile t+1 into registers while computing tile t
        const int r0 = tid >> 2,         kq0 = (tid & 3) << 2;
        const int r1 = (tid + 256) >> 2, kq1 = ((tid + 256) & 3) << 2;
        float4 ra0, ra1, rb0, rb1;
        ra0 = *(const float4*)&Ab[(size_t)(rt0 + r0) * K + kq0];
        rb0 = *(const float4*)&Bb[(size_t)(ct0 + r0) * K + kq0];
        ra1 = *(const float4*)&Ab[(size_t)(rt0 + r1) * K + kq1];
        rb1 = *(const float4*)&Bb[(size_t)(ct0 + r1) * K + kq1];
#pragma unroll
        for (int t = 0; t < NT; ++t) {
            sA[kq0 + 0][r0] = ra0.x; sA[kq0 + 1][r0] = ra0.y;
            sA[kq0 + 2][r0] = ra0.z; sA[kq0 + 3][r0] = ra0.w;
            sB[kq0 + 0][r0] = rb0.x; sB[kq0 + 1][r0] = rb0.y;
            sB[kq0 + 2][r0] = rb0.z; sB[kq0 + 3][r0] = rb0.w;
            sA[kq1 + 0][r1] = ra1.x; sA[kq1 + 1][r1] = ra1.y;
            sA[kq1 + 2][r1] = ra1.z; sA[kq1 + 3][r1] = ra1.w;
            sB[kq1 + 0][r1] = rb1.x; sB[kq1 + 1][r1] = rb1.y;
            sB[kq1 + 2][r1] = rb1.z; sB[kq1 + 3][r1] = rb1.w;
            __syncthreads();
            if (t + 1 < NT) {
                const int kg = (t + 1) * 16;
                ra0 = *(const float4*)&Ab[(size_t)(rt0 + r0) * K + kg + kq0];
                rb0 = *(const float4*)&Bb[(size_t)(ct0 + r0) * K + kg + kq0];
                ra1 = *(const float4*)&Ab[(size_t)(rt0 + r1) * K + kg + kq1];
                rb1 = *(const float4*)&Bb[(size_t)(ct0 + r1) * K + kg + kq1];
            }
#pragma unroll
            for (int kk = 0; kk < 16; ++kk) {
                float a[8], bb[8];
                *(float4*)&a[0]  = *(const float4*)&sA[kk][ty * 8];
                *(float4*)&a[4]  = *(const float4*)&sA[kk][ty * 8 + 4];
                *(float4*)&bb[0] = *(const float4*)&sB[kk][tx * 8];
                *(float4*)&bb[4] = *(const float4*)&sB[kk][tx * 8 + 4];
#pragma unroll
                for (int i2 = 0; i2 < 8; ++i2)
#pragma unroll
                    for (int j2 = 0; j2 < 8; ++j2)
                        acc[i2][j2] += a[i2] * bb[j2];
            }
            __syncthreads();
        }
    }

    if (DIST) {
        const float* nfb = nf + (size_t)bz * NPTS;
        float nmv[8];
        *(float4*)&nmv[0] = *(const float4*)&nfb[ct0 + tx * 8];
        *(float4*)&nmv[4] = *(const float4*)&nfb[ct0 + tx * 8 + 4];
#pragma unroll
        for (int i2 = 0; i2 < 8; ++i2) {
            float4 o0, o1;
            o0.x = 2.f * acc[i2][0] - nmv[0]; o0.y = 2.f * acc[i2][1] - nmv[1];
            o0.z = 2.f * acc[i2][2] - nmv[2]; o0.w = 2.f * acc[i2][3] - nmv[3];
            o1.x = 2.f * acc[i2][4] - nmv[4]; o1.y = 2.f * acc[i2][5] - nmv[5];
            o1.z = 2.f * acc[i2][6] - nmv[6]; o1.w = 2.f * acc[i2][7] - nmv[7];
            float* dst = Y + ((size_t)bz * NPTS + rt0 + ty * 8 + i2) * NPTS + ct0 + tx * 8;
            *(float4*)&dst[0] = o0;
            *(float4*)&dst[4] = o1;
        }
    } else {
#pragma unroll
        for (int i2 = 0; i2 < 8; ++i2) {
            float* dst = Y + (size_t)(rt0 + ty * 8 + i2) * N + ct0 + tx * 8;
            *(float4*)&dst[0] = make_float4(acc[i2][0], acc[i2][1], acc[i2][2], acc[i2][3]);
            *(float4*)&dst[4] = make_float4(acc[i2][4], acc[i2][5], acc[i2][6], acc[i2][7]);
        }
    }
}

// ---------------- selection: warp per row; m4 prefilter + top-4 cache + pops + exact rescan ----
// D points at this batch's slice; cand at this batch's slice.
__global__ void __launch_bounds__(256)
select16(const float* __restrict__ D, int* __restrict__ cand) {
    const unsigned FULL = 0xffffffffu;
    const int warp = threadIdx.x >> 5, lane = threadIdx.x & 31;
    const int point = blockIdx.x * 8 + warp;   // row within batch
    const float4* rowv = (const float4*)(D + (size_t)point * NPTS);

    float v[4]; int id[4];
#pragma unroll
    for (int q = 0; q < 4; ++q) { v[q] = -INFINITY; id[q] = 0x7fffffff; }

#pragma unroll
    for (int t = 0; t < NPTS / 128; ++t) {
        float4 qv = rowv[t * 32 + lane];
        float m4 = fmaxf(fmaxf(qv.x, qv.y), fmaxf(qv.z, qv.w));
        if (m4 > v[3]) {
            const int base = (t * 32 + lane) * 4;
            ins4(v, id, qv.x, base);
            ins4(v, id, qv.y, base + 1);
            ins4(v, id, qv.z, base + 2);
            ins4(v, id, qv.w, base + 3);
        }
    }

    int em[KSEL];
    int* out = cand + (size_t)point * KSEL;
#pragma unroll 1
    for (int r = 0; r < KSEL; ++r) {
        if (v[0] == -INFINITY) {
            // cache exhausted for this lane: exact refill excluding emitted ids
            for (int t = 0; t < NPTS / 128; ++t) {
                float4 qv = rowv[t * 32 + lane];
                const int base = (t * 32 + lane) * 4;
                float qq[4] = {qv.x, qv.y, qv.z, qv.w};
#pragma unroll
                for (int j = 0; j < 4; ++j) {
                    const int m = base + j;
                    bool skip = false;
                    for (int e = 0; e < r; ++e) skip |= (em[e] == m);
                    if (!skip) ins4(v, id, qq[j], m);
                }
            }
        }
        float vv = v[0]; int ii = id[0];
#pragma unroll
        for (int off = 16; off; off >>= 1) {
            float ov = __shfl_down_sync(FULL, vv, off);
            int   oi = __shfl_down_sync(FULL, ii, off);
            if (ov > vv || (ov == vv && oi < ii)) { vv = ov; ii = oi; }
        }
        const int bi = __shfl_sync(FULL, ii, 0);
        em[r] = bi;
        if (lane == 0) out[r] = bi;
        if (id[0] == bi) {   // owner lane pops (indices unique per lane)
#pragma unroll
            for (int q = 0; q < 3; ++q) { v[q] = v[q + 1]; id[q] = id[q + 1]; }
            v[3] = -INFINITY; id[3] = 0x7fffffff;
        }
    }
}

// ---------------- kNN pass 2: fp64 exact rescore of top-16, keep true top-10 ----------------
template <int C>
__global__ void rerank(const float* __restrict__ x, const double* __restrict__ nrm,
                       const int* __restrict__ cand, int* __restrict__ idxout) {
    const unsigned FULL = 0xffffffffu;
    __shared__ float s_cent[8][C];
    const int warp = threadIdx.x >> 5, lane = threadIdx.x & 31;
    const int point = blockIdx.x * 8 + warp;          // global b*NPTS+n
    const int browbase = point & ~(NPTS - 1);
    const float* xb = x + (size_t)browbase * C;
    const int nloc = point - browbase;

    for (int c = lane; c < C; c += 32) s_cent[warp][c] = xb[(size_t)nloc * C + c];
    __syncwarp();

    double d = -INFINITY;
    int mi = 0x7fffffff;
    if (lane < KSEL) {
        mi = cand[(size_t)point * KSEL + lane];
        const float* row = xb + (size_t)mi * C;
        if (C % 4 == 0) {
            double a0 = 0.0, a1 = 0.0, a2 = 0.0, a3 = 0.0;
#pragma unroll
            for (int c = 0; c < C; c += 4) {
                float4 r = *(const float4*)&row[c];
                a0 += (double)s_cent[warp][c + 0] * (double)r.x;
                a1 += (double)s_cent[warp][c + 1] * (double)r.y;
                a2 += (double)s_cent[warp][c + 2] * (double)r.z;
                a3 += (double)s_cent[warp][c + 3] * (double)r.w;
            }
            d = 2.0 * ((a0 + a1) + (a2 + a3)) - nrm[point] - nrm[browbase + mi];
        } else {
            double dot = 0.0;
#pragma unroll
            for (int c = 0; c < C; ++c)
                dot += (double)s_cent[warp][c] * (double)row[c];
            d = 2.0 * dot - nrm[point] - nrm[browbase + mi];
        }
    }

    int* out = idxout + (size_t)point * KNB;
#pragma unroll
    for (int r = 0; r < KNB; ++r) {
        double v = d; int i_ = mi;
#pragma unroll
        for (int off = 16; off; off >>= 1) {
            double ov = __shfl_down_sync(FULL, v, off);
            int    oi = __shfl_down_sync(FULL, i_, off);
            if (ov > v || (ov == v && oi < i_)) { v = ov; i_ = oi; }
        }
        double bv = __shfl_sync(FULL, v, 0);
        int    bi = __shfl_sync(FULL, i_, 0);
        if (lane == 0) out[r] = bi;
        if (d == bv && mi == bi) d = -INFINITY;
    }
}

// ---------------- weight prep: Wp = [A ; B - A] ----------------
__global__ void prep_w(const float* __restrict__ w, float* __restrict__ wp, int O, int C) {
    int i = blockIdx.x * 256 + threadIdx.x;
    if (i < O * C) {
        int o = i / C, c = i % C;
        float a = w[(size_t)o * 2 * C + c];
        wp[i] = a;
        wp[(size_t)O * C + i] = w[(size_t)o * 2 * C + C + c] - a;
    }
}

// ---------------- gather + reduce + BN + lrelu ----------------
__global__ void edge_reduce(const float* __restrict__ yz, const int* __restrict__ idx,
                            const float* __restrict__ gg, const float* __restrict__ bb,
                            const float* __restrict__ rm, const float* __restrict__ rv,
                            float* __restrict__ xout, int O) {
    const int bn = blockIdx.x;
    const int b = bn >> 11;
    const int o = threadIdx.x;
    __shared__ int sj[KNB];
    if (o < KNB) sj[o] = idx[(size_t)bn * KNB + o];
    __syncthreads();
    const double scale = (double)gg[o] / sqrt((double)rv[o] + 1e-5);
    const int twoO = 2 * O;
    const float z = yz[(size_t)bn * twoO + O + o];
    const int browbase = b << 11;
    float red;
    if (scale >= 0.0) {
        red = -INFINITY;
#pragma unroll
        for (int j = 0; j < KNB; ++j)
            red = fmaxf(red, yz[(size_t)(browbase + sj[j]) * twoO + o]);
    } else {
        red = INFINITY;
#pragma unroll
        for (int j = 0; j < KNB; ++j)
            red = fminf(red, yz[(size_t)(browbase + sj[j]) * twoO + o]);
    }
    double h = (((double)red + (double)z) - (double)rm[o]) * scale + (double)bb[o];
    float hf = (float)h;
    float r = hf >= 0.f ? hf : 0.2f * hf;
    xout[(size_t)bn * O + o] = r;
}

// ---------------- tiled transpose: x4 [B*NPTS,256] -> outT [B,256,NPTS] ----------------
__global__ void transpose_x4(const float* __restrict__ src, float* __restrict__ dst) {
    __shared__ float t[32][33];
    const int b = blockIdx.z;
    const int n0 = blockIdx.x * 32, o0 = blockIdx.y * 32;
    const int lx = threadIdx.x, ly = threadIdx.y;
    for (int i = ly; i < 32; i += 8)
        t[i][lx] = src[((size_t)(b * NPTS + n0 + i)) * 256 + o0 + lx];
    __syncthreads();
    for (int i = ly; i < 32; i += 8)
        dst[((size_t)(b * 256 + o0 + i)) * NPTS + n0 + lx] = t[lx][i];
}

// ---------------- global max (two pass) ----------------
__global__ void gmax_partial(const float* __restrict__ x1, const float* __restrict__ x2,
                             const float* __restrict__ x3, const float* __restrict__ x4,
                             float* __restrict__ part) {
    const int b = blockIdx.x, chunk = blockIdx.y;
    const int c = threadIdx.x;  // 0..511
    const float* src; int O, off;
    if (c < 64)       { src = x1; O = 64;  off = c; }
    else if (c < 128) { src = x2; O = 64;  off = c - 64; }
    else if (c < 256) { src = x3; O = 128; off = c - 128; }
    else              { src = x4; O = 256; off = c - 256; }
    float m = -INFINITY;
    const int nbeg = chunk * 128;
    const float* p = src + ((size_t)b * NPTS + nbeg) * O + off;
    for (int n = 0; n < 128; ++n) m = fmaxf(m, p[(size_t)n * O]);
    part[((size_t)b * 16 + chunk) * 512 + c] = m;
}

__global__ void gmax_final(const float* __restrict__ part, float* __restrict__ gmax) {
    const int b = blockIdx.x, c = threadIdx.x;
    float m = -INFINITY;
    for (int ch = 0; ch < 16; ++ch)
        m = fmaxf(m, part[((size_t)b * 16 + ch) * 512 + c]);
    gmax[(size_t)b * 512 + c] = m;
}

// ---------------- final FC + BN + lrelu (fp64 accumulate) ----------------
__global__ void final_fc(const float* __restrict__ gmax, const float* __restrict__ lw,
                         const float* __restrict__ lb, const float* __restrict__ g5,
                         const float* __restrict__ b5, const float* __restrict__ rm5,
                         const float* __restrict__ rv5, float* __restrict__ out) {
    const int b = blockIdx.y;
    const int o = blockIdx.x * 256 + threadIdx.x;
    __shared__ float sg[512];
    for (int i = threadIdx.x; i < 512; i += 256) sg[i] = gmax[(size_t)b * 512 + i];
    __syncthreads();
    const float* wrow = lw + (size_t)o * 512;
    double acc = 0.0;
#pragma unroll 8
    for (int c = 0; c < 512; ++c) acc += (double)sg[c] * (double)wrow[c];
    acc += (double)lb[o];
    const double scale = (double)g5[o] / sqrt((double)rv5[o] + 1e-5);
    double h = (acc - (double)rm5[o]) * scale + (double)b5[o];
    float hf = (float)h;
    out[(size_t)b * 1024 + o] = hf >= 0.f ? hf : 0.2f * hf;
}

// ---------------- per-layer driver: dist+select per batch for L2 locality ----------------
template <int C>
static void knn_layer(const float* xin, float* dist, float* nrmf, double* nrm,
                      int* cand, int* idx) {
    const dim3 dist_grid_b(NPTS / 128, NPTS / 128, 1);
    for (int b = 0; b < B_; ++b) {
        const float* xb = xin + (size_t)b * NPTS * C;
        float* db = dist + (size_t)b * NPTS * NPTS;
        gemm128<C, true><<<dist_grid_b, 256>>>(xb, nullptr, nrmf + (size_t)b * NPTS, db, NPTS);
        select16<<<NPTS / 8, 256>>>(db, cand + (size_t)b * NPTS * KSEL);
    }
    rerank<C><<<MTOT / 8, 256>>>(xin, nrm, cand, idx);
}

// ---------------- launch ----------------
extern "C" void kernel_launch(void* const* d_in, const int* in_sizes, int n_in,
                              void* d_out, int out_size) {
    const float* x    = (const float*)d_in[0];
    const float* w1   = (const float*)d_in[1];
    const float* g1   = (const float*)d_in[2];
    const float* b1   = (const float*)d_in[3];
    const float* rm1  = (const float*)d_in[4];
    const float* rv1  = (const float*)d_in[5];
    const float* w2   = (const float*)d_in[6];
    const float* g2   = (const float*)d_in[7];
    const float* b2   = (const float*)d_in[8];
    const float* rm2  = (const float*)d_in[9];
    const float* rv2  = (const float*)d_in[10];
    const float* w3   = (const float*)d_in[11];
    const float* g3   = (const float*)d_in[12];
    const float* b3   = (const float*)d_in[13];
    const float* rm3  = (const float*)d_in[14];
    const float* rv3  = (const float*)d_in[15];
    const float* w4   = (const float*)d_in[16];
    const float* g4   = (const float*)d_in[17];
    const float* b4   = (const float*)d_in[18];
    const float* rm4  = (const float*)d_in[19];
    const float* rv4  = (const float*)d_in[20];
    const float* lw   = (const float*)d_in[21];
    const float* lb   = (const float*)d_in[22];
    const float* g5   = (const float*)d_in[23];
    const float* b5   = (const float*)d_in[24];
    const float* rm5  = (const float*)d_in[25];
    const float* rv5  = (const float*)d_in[26];

    float *x1, *x2, *x3, *x4, *yz, *wp, *part, *gmax, *dist, *nrmf;
    int *idx, *cand;
    double* nrm;
    cudaGetSymbolAddress((void**)&x1, d_x1);
    cudaGetSymbolAddress((void**)&x2, d_x2);
    cudaGetSymbolAddress((void**)&x3, d_x3);
    cudaGetSymbolAddress((void**)&x4, d_x4);
    cudaGetSymbolAddress((void**)&yz, d_yz);
    cudaGetSymbolAddress((void**)&dist, d_dist);
    cudaGetSymbolAddress((void**)&idx, d_idxbuf);
    cudaGetSymbolAddress((void**)&cand, d_cand);
    cudaGetSymbolAddress((void**)&nrm, d_norm);
    cudaGetSymbolAddress((void**)&nrmf, d_normf);
    cudaGetSymbolAddress((void**)&wp, d_wp);
    cudaGetSymbolAddress((void**)&part, d_part);
    cudaGetSymbolAddress((void**)&gmax, d_gmax);

    float* out = (float*)d_out;
    float* x4T = out + B_ * 1024;

    const int nrm_blocks = (MTOT * 32 + 255) / 256;

    // layer 1: C=5 -> O=64  (capture slot #4 = first per-batch dist gemm)
    compute_norms<5><<<nrm_blocks, 256>>>(x, nrm, nrmf);
    prep_w<<<(64 * 5 + 255) / 256, 256>>>(w1, wp, 64, 5);
    gemm128<5, false><<<dim3(1, MTOT / 128, 1), 256>>>(x, wp, nullptr, yz, 128);
    knn_layer<5>(x, dist, nrmf, nrm, cand, idx);
    edge_reduce<<<MTOT, 64>>>(yz, idx, g1, b1, rm1, rv1, x1, 64);

    // layer 2: C=64 -> O=64
    compute_norms<64><<<nrm_blocks, 256>>>(x1, nrm, nrmf);
    prep_w<<<(64 * 64 + 255) / 256, 256>>>(w2, wp, 64, 64);
    gemm128<64, false><<<dim3(1, MTOT / 128, 1), 256>>>(x1, wp, nullptr, yz, 128);
    knn_layer<64>(x1, dist, nrmf, nrm, cand, idx);
    edge_reduce<<<MTOT, 64>>>(yz, idx, g2, b2, rm2, rv2, x2, 64);

    // layer 3: C=64 -> O=128
    compute_norms<64><<<nrm_blocks, 256>>>(x2, nrm, nrmf);
    prep_w<<<(128 * 64 + 255) / 256, 256>>>(w3, wp, 128, 64);
    gemm128<64, false><<<dim3(2, MTOT / 128, 1), 256>>>(x2, wp, nullptr, yz, 256);
    knn_layer<64>(x2, dist, nrmf, nrm, cand, idx);
    edge_reduce<<<MTOT, 128>>>(yz, idx, g3, b3, rm3, rv3, x3, 128);

    // layer 4: C=128 -> O=256
    compute_norms<128><<<nrm_blocks, 256>>>(x3, nrm, nrmf);
    prep_w<<<(256 * 128 + 255) / 256, 256>>>(w4, wp, 256, 128);
    gemm128<128, false><<<dim3(4, MTOT / 128, 1), 256>>>(x3, wp, nullptr, yz, 512);
    knn_layer<128>(x3, dist, nrmf, nrm, cand, idx);
    edge_reduce<<<MTOT, 256>>>(yz, idx, g4, b4, rm4, rv4, x4, 256);
    transpose_x4<<<dim3(NPTS / 32, 256 / 32, B_), dim3(32, 8)>>>(x4, x4T);

    // global max + final FC
    gmax_partial<<<dim3(B_, 16), 512>>>(x1, x2, x3, x4, part);
    gmax_final<<<B_, 512>>>(part, gmax);
    final_fc<<<dim3(4, B_), 256>>>(gmax, lw, lb, g5, b5, rm5, rv5, out);
}

// round 15
// speedup vs baseline: 1.1780x; 1.1780x over previous
#include <cuda_runtime.h>
#include <math.h>

#define B_ 8
#define NPTS 2048
#define KNB 10
#define KSEL 16
#define EPSV 1e-5f
#define MTOT (B_ * NPTS)

// ---------------- scratch (no allocation allowed) ----------------
__device__ float  d_x1[MTOT * 64];
__device__ float  d_x2[MTOT * 64];
__device__ float  d_x3[MTOT * 128];
__device__ float  d_x4[MTOT * 256];
__device__ float  d_yz[MTOT * 512];
__device__ float  d_dist[(size_t)MTOT * NPTS];   // 134 MB ranking scores
__device__ int    d_idxbuf[MTOT * KNB];
__device__ int    d_cand[MTOT * KSEL];
__device__ double d_norm[MTOT];
__device__ float  d_normf[MTOT];
__device__ float  d_wp[512 * 128];
__device__ float  d_part[B_ * 16 * 512];
__device__ float  d_gmax[B_ * 512];

// ---------------- helpers ----------------
__device__ __forceinline__ void ins4(float v[4], int id[4], float d, int m) {
    if (d > v[3]) {
        float cv = d; int ci = m;
#pragma unroll
        for (int p = 0; p < 4; ++p) {
            if (cv > v[p]) {
                float t = v[p]; v[p] = cv; cv = t;
                int u = id[p]; id[p] = ci; ci = u;
            }
        }
    }
}

// ---------------- point norms: one warp per point; fp64 (rerank) + fp32 (pass-1) ----------------
template <int C>
__global__ void compute_norms(const float* __restrict__ x, double* __restrict__ nrm,
                              float* __restrict__ nrmf) {
    const unsigned FULL = 0xffffffffu;
    const int gw = (blockIdx.x * 256 + threadIdx.x) >> 5;
    const int lane = threadIdx.x & 31;
    if (gw >= MTOT) return;
    const float* p = x + (size_t)gw * C;
    double s = 0.0;
#pragma unroll
    for (int c = lane; c < C; c += 32) { double v = (double)p[c]; s += v * v; }
#pragma unroll
    for (int off = 16; off; off >>= 1) s += __shfl_down_sync(FULL, s, off);
    if (lane == 0) { nrm[gw] = s; nrmf[gw] = (float)s; }
}

// ---------------- 128x128 tile GEMM, 8x8 microtile, 256 thr, double-buffered k-loop ----------
// DIST=true : Y[(bz*NPTS + n)*NPTS + m] = 2*<x_n, x_m> - ||x_m||^2  (grid (16,16,B))
// DIST=false: Y[n*N + m] = <X_n, W_m>                                (grid (N/128, MTOT/128, 1))
template <int K, bool DIST>
__global__ void __launch_bounds__(256)
gemm128(const float* __restrict__ A, const float* __restrict__ Bw,
        const float* __restrict__ nf, float* __restrict__ Y, int N) {
    __shared__ float sA[16][132];
    __shared__ float sB[16][132];
    const int bz = blockIdx.z;
    const float* Ab = A + (DIST ? (size_t)bz * NPTS * K : (size_t)0);
    const float* Bb = DIST ? Ab : Bw;
    const int rt0 = blockIdx.y * 128;   // output rows (n)
    const int ct0 = blockIdx.x * 128;   // output cols (m)
    const int tid = threadIdx.x;
    const int tx = tid & 15, ty = tid >> 4;

    float acc[8][8] = {};
    constexpr int NT = (K + 15) / 16;

    if (NT == 1) {
        // single k-tile path (K=5)
        for (int i = tid; i < 2048; i += 256) {
            int r = i >> 4, k = i & 15;
            sA[k][r] = (k < K) ? Ab[(size_t)(rt0 + r) * K + k] : 0.f;
            sB[k][r] = (k < K) ? Bb[(size_t)(ct0 + r) * K + k] : 0.f;
        }
        __syncthreads();
#pragma unroll
        for (int kk = 0; kk < 16; ++kk) {
            float a[8], bb[8];
            *(float4*)&a[0]  = *(const float4*)&sA[kk][ty * 8];
            *(float4*)&a[4]  = *(const float4*)&sA[kk][ty * 8 + 4];
            *(float4*)&bb[0] = *(const float4*)&sB[kk][tx * 8];
            *(float4*)&bb[4] = *(const float4*)&sB[kk][tx * 8 + 4];
#pragma unroll
            for (int i2 = 0; i2 < 8; ++i2)
#pragma unroll
                for (int j2 = 0; j2 < 8; ++j2)
                    acc[i2][j2] += a[i2] * bb[j2];
        }
        __syncthreads();
    } else {
        // double-buffered: prefetch tile t+1 into registers while computing tile t
        const int r0 = tid >> 2,         kq0 = (tid & 3) << 2;
        const int r1 = (tid + 256) >> 2, kq1 = ((tid + 256) & 3) << 2;
        float4 ra0, ra1, rb0, rb1;
        ra0 = *(const float4*)&Ab[(size_t)(rt0 + r0) * K + kq0];
        rb0 = *(const float4*)&Bb[(size_t)(ct0 + r0) * K + kq0];
        ra1 = *(const float4*)&Ab[(size_t)(rt0 + r1) * K + kq1];
        rb1 = *(const float4*)&Bb[(size_t)(ct0 + r1) * K + kq1];
#pragma unroll
        for (int t = 0; t < NT; ++t) {
            sA[kq0 + 0][r0] = ra0.x; sA[kq0 + 1][r0] = ra0.y;
            sA[kq0 + 2][r0] = ra0.z; sA[kq0 + 3][r0] = ra0.w;
            sB[kq0 + 0][r0] = rb0.x; sB[kq0 + 1][r0] = rb0.y;
            sB[kq0 + 2][r0] = rb0.z; sB[kq0 + 3][r0] = rb0.w;
            sA[kq1 + 0][r1] = ra1.x; sA[kq1 + 1][r1] = ra1.y;
            sA[kq1 + 2][r1] = ra1.z; sA[kq1 + 3][r1] = ra1.w;
            sB[kq1 + 0][r1] = rb1.x; sB[kq1 + 1][r1] = rb1.y;
            sB[kq1 + 2][r1] = rb1.z; sB[kq1 + 3][r1] = rb1.w;
            __syncthreads();
            if (t + 1 < NT) {
                const int kg = (t + 1) * 16;
                ra0 = *(const float4*)&Ab[(size_t)(rt0 + r0) * K + kg + kq0];
                rb0 = *(const float4*)&Bb[(size_t)(ct0 + r0) * K + kg + kq0];
                ra1 = *(const float4*)&Ab[(size_t)(rt0 + r1) * K + kg + kq1];
                rb1 = *(const float4*)&Bb[(size_t)(ct0 + r1) * K + kg + kq1];
            }
#pragma unroll
            for (int kk = 0; kk < 16; ++kk) {
                float a[8], bb[8];
                *(float4*)&a[0]  = *(const float4*)&sA[kk][ty * 8];
                *(float4*)&a[4]  = *(const float4*)&sA[kk][ty * 8 + 4];
                *(float4*)&bb[0] = *(const float4*)&sB[kk][tx * 8];
                *(float4*)&bb[4] = *(const float4*)&sB[kk][tx * 8 + 4];
#pragma unroll
                for (int i2 = 0; i2 < 8; ++i2)
#pragma unroll
                    for (int j2 = 0; j2 < 8; ++j2)
                        acc[i2][j2] += a[i2] * bb[j2];
            }
            __syncthreads();
        }
    }

    if (DIST) {
        const float* nfb = nf + (size_t)bz * NPTS;
        float nmv[8];
        *(float4*)&nmv[0] = *(const float4*)&nfb[ct0 + tx * 8];
        *(float4*)&nmv[4] = *(const float4*)&nfb[ct0 + tx * 8 + 4];
#pragma unroll
        for (int i2 = 0; i2 < 8; ++i2) {
            float4 o0, o1;
            o0.x = 2.f * acc[i2][0] - nmv[0]; o0.y = 2.f * acc[i2][1] - nmv[1];
            o0.z = 2.f * acc[i2][2] - nmv[2]; o0.w = 2.f * acc[i2][3] - nmv[3];
            o1.x = 2.f * acc[i2][4] - nmv[4]; o1.y = 2.f * acc[i2][5] - nmv[5];
            o1.z = 2.f * acc[i2][6] - nmv[6]; o1.w = 2.f * acc[i2][7] - nmv[7];
            float* dst = Y + ((size_t)bz * NPTS + rt0 + ty * 8 + i2) * NPTS + ct0 + tx * 8;
            *(float4*)&dst[0] = o0;
            *(float4*)&dst[4] = o1;
        }
    } else {
#pragma unroll
        for (int i2 = 0; i2 < 8; ++i2) {
            float* dst = Y + (size_t)(rt0 + ty * 8 + i2) * N + ct0 + tx * 8;
            *(float4*)&dst[0] = make_float4(acc[i2][0], acc[i2][1], acc[i2][2], acc[i2][3]);
            *(float4*)&dst[4] = make_float4(acc[i2][4], acc[i2][5], acc[i2][6], acc[i2][7]);
        }
    }
}

// ---------------- selection: warp per row; m4 prefilter + top-4 cache + pops + exact rescan ----
__global__ void __launch_bounds__(256)
select16(const float* __restrict__ D, int* __restrict__ cand) {
    const unsigned FULL = 0xffffffffu;
    const int warp = threadIdx.x >> 5, lane = threadIdx.x & 31;
    const int point = blockIdx.x * 8 + warp;   // global b*NPTS+n
    const float4* rowv = (const float4*)(D + (size_t)point * NPTS);

    float v[4]; int id[4];
#pragma unroll
    for (int q = 0; q < 4; ++q) { v[q] = -INFINITY; id[q] = 0x7fffffff; }

#pragma unroll
    for (int t = 0; t < NPTS / 128; ++t) {
        float4 qv = rowv[t * 32 + lane];
        float m4 = fmaxf(fmaxf(qv.x, qv.y), fmaxf(qv.z, qv.w));
        if (m4 > v[3]) {
            const int base = (t * 32 + lane) * 4;
            ins4(v, id, qv.x, base);
            ins4(v, id, qv.y, base + 1);
            ins4(v, id, qv.z, base + 2);
            ins4(v, id, qv.w, base + 3);
        }
    }

    int em[KSEL];
    int* out = cand + (size_t)point * KSEL;
#pragma unroll 1
    for (int r = 0; r < KSEL; ++r) {
        if (v[0] == -INFINITY) {
            // cache exhausted for this lane: exact refill excluding emitted ids
            for (int t = 0; t < NPTS / 128; ++t) {
                float4 qv = rowv[t * 32 + lane];
                const int base = (t * 32 + lane) * 4;
                float qq[4] = {qv.x, qv.y, qv.z, qv.w};
#pragma unroll
                for (int j = 0; j < 4; ++j) {
                    const int m = base + j;
                    bool skip = false;
                    for (int e = 0; e < r; ++e) skip |= (em[e] == m);
                    if (!skip) ins4(v, id, qq[j], m);
                }
            }
        }
        float vv = v[0]; int ii = id[0];
#pragma unroll
        for (int off = 16; off; off >>= 1) {
            float ov = __shfl_down_sync(FULL, vv, off);
            int   oi = __shfl_down_sync(FULL, ii, off);
            if (ov > vv || (ov == vv && oi < ii)) { vv = ov; ii = oi; }
        }
        const int bi = __shfl_sync(FULL, ii, 0);
        em[r] = bi;
        if (lane == 0) out[r] = bi;
        if (id[0] == bi) {   // owner lane pops (indices unique per lane)
#pragma unroll
            for (int q = 0; q < 3; ++q) { v[q] = v[q + 1]; id[q] = id[q + 1]; }
            v[3] = -INFINITY; id[3] = 0x7fffffff;
        }
    }
}

// ---------------- kNN pass 2: fp64 exact rescore of top-16, keep true top-10 ----------------
template <int C>
__global__ void rerank(const float* __restrict__ x, const double* __restrict__ nrm,
                       const int* __restrict__ cand, int* __restrict__ idxout) {
    const unsigned FULL = 0xffffffffu;
    __shared__ float s_cent[8][C];
    const int warp = threadIdx.x >> 5, lane = threadIdx.x & 31;
    const int point = blockIdx.x * 8 + warp;          // global b*NPTS+n
    const int browbase = point & ~(NPTS - 1);
    const float* xb = x + (size_t)browbase * C;
    const int nloc = point - browbase;

    for (int c = lane; c < C; c += 32) s_cent[warp][c] = xb[(size_t)nloc * C + c];
    __syncwarp();

    double d = -INFINITY;
    int mi = 0x7fffffff;
    if (lane < KSEL) {
        mi = cand[(size_t)point * KSEL + lane];
        const float* row = xb + (size_t)mi * C;
        if (C % 4 == 0) {
            double a0 = 0.0, a1 = 0.0, a2 = 0.0, a3 = 0.0;
#pragma unroll
            for (int c = 0; c < C; c += 4) {
                float4 r = *(const float4*)&row[c];
                a0 += (double)s_cent[warp][c + 0] * (double)r.x;
                a1 += (double)s_cent[warp][c + 1] * (double)r.y;
                a2 += (double)s_cent[warp][c + 2] * (double)r.z;
                a3 += (double)s_cent[warp][c + 3] * (double)r.w;
            }
            d = 2.0 * ((a0 + a1) + (a2 + a3)) - nrm[point] - nrm[browbase + mi];
        } else {
            double dot = 0.0;
#pragma unroll
            for (int c = 0; c < C; ++c)
                dot += (double)s_cent[warp][c] * (double)row[c];
            d = 2.0 * dot - nrm[point] - nrm[browbase + mi];
        }
    }

    int* out = idxout + (size_t)point * KNB;
#pragma unroll
    for (int r = 0; r < KNB; ++r) {
        double v = d; int i_ = mi;
#pragma unroll
        for (int off = 16; off; off >>= 1) {
            double ov = __shfl_down_sync(FULL, v, off);
            int    oi = __shfl_down_sync(FULL, i_, off);
            if (ov > v || (ov == v && oi < i_)) { v = ov; i_ = oi; }
        }
        double bv = __shfl_sync(FULL, v, 0);
        int    bi = __shfl_sync(FULL, i_, 0);
        if (lane == 0) out[r] = bi;
        if (d == bv && mi == bi) d = -INFINITY;
    }
}

// ---------------- weight prep: Wp = [A ; B - A] ----------------
__global__ void prep_w(const float* __restrict__ w, float* __restrict__ wp, int O, int C) {
    int i = blockIdx.x * 256 + threadIdx.x;
    if (i < O * C) {
        int o = i / C, c = i % C;
        float a = w[(size_t)o * 2 * C + c];
        wp[i] = a;
        wp[(size_t)O * C + i] = w[(size_t)o * 2 * C + C + c] - a;
    }
}

// ---------------- gather + reduce + BN + lrelu ----------------
__global__ void edge_reduce(const float* __restrict__ yz, const int* __restrict__ idx,
                            const float* __restrict__ gg, const float* __restrict__ bb,
                            const float* __restrict__ rm, const float* __restrict__ rv,
                            float* __restrict__ xout, int O) {
    const int bn = blockIdx.x;
    const int b = bn >> 11;
    const int o = threadIdx.x;
    __shared__ int sj[KNB];
    if (o < KNB) sj[o] = idx[(size_t)bn * KNB + o];
    __syncthreads();
    const double scale = (double)gg[o] / sqrt((double)rv[o] + 1e-5);
    const int twoO = 2 * O;
    const float z = yz[(size_t)bn * twoO + O + o];
    const int browbase = b << 11;
    float red;
    if (scale >= 0.0) {
        red = -INFINITY;
#pragma unroll
        for (int j = 0; j < KNB; ++j)
            red = fmaxf(red, yz[(size_t)(browbase + sj[j]) * twoO + o]);
    } else {
        red = INFINITY;
#pragma unroll
        for (int j = 0; j < KNB; ++j)
            red = fminf(red, yz[(size_t)(browbase + sj[j]) * twoO + o]);
    }
    double h = (((double)red + (double)z) - (double)rm[o]) * scale + (double)bb[o];
    float hf = (float)h;
    float r = hf >= 0.f ? hf : 0.2f * hf;
    xout[(size_t)bn * O + o] = r;
}

// ---------------- tiled transpose: x4 [B*NPTS,256] -> outT [B,256,NPTS] ----------------
__global__ void transpose_x4(const float* __restrict__ src, float* __restrict__ dst) {
    __shared__ float t[32][33];
    const int b = blockIdx.z;
    const int n0 = blockIdx.x * 32, o0 = blockIdx.y * 32;
    const int lx = threadIdx.x, ly = threadIdx.y;
    for (int i = ly; i < 32; i += 8)
        t[i][lx] = src[((size_t)(b * NPTS + n0 + i)) * 256 + o0 + lx];
    __syncthreads();
    for (int i = ly; i < 32; i += 8)
        dst[((size_t)(b * 256 + o0 + i)) * NPTS + n0 + lx] = t[lx][i];
}

// ---------------- global max (two pass) ----------------
__global__ void gmax_partial(const float* __restrict__ x1, const float* __restrict__ x2,
                             const float* __restrict__ x3, const float* __restrict__ x4,
                             float* __restrict__ part) {
    const int b = blockIdx.x, chunk = blockIdx.y;
    const int c = threadIdx.x;  // 0..511
    const float* src; int O, off;
    if (c < 64)       { src = x1; O = 64;  off = c; }
    else if (c < 128) { src = x2; O = 64;  off = c - 64; }
    else if (c < 256) { src = x3; O = 128; off = c - 128; }
    else              { src = x4; O = 256; off = c - 256; }
    float m = -INFINITY;
    const int nbeg = chunk * 128;
    const float* p = src + ((size_t)b * NPTS + nbeg) * O + off;
    for (int n = 0; n < 128; ++n) m = fmaxf(m, p[(size_t)n * O]);
    part[((size_t)b * 16 + chunk) * 512 + c] = m;
}

__global__ void gmax_final(const float* __restrict__ part, float* __restrict__ gmax) {
    const int b = blockIdx.x, c = threadIdx.x;
    float m = -INFINITY;
    for (int ch = 0; ch < 16; ++ch)
        m = fmaxf(m, part[((size_t)b * 16 + ch) * 512 + c]);
    gmax[(size_t)b * 512 + c] = m;
}

// ---------------- final FC + BN + lrelu (fp64 accumulate) ----------------
__global__ void final_fc(const float* __restrict__ gmax, const float* __restrict__ lw,
                         const float* __restrict__ lb, const float* __restrict__ g5,
                         const float* __restrict__ b5, const float* __restrict__ rm5,
                         const float* __restrict__ rv5, float* __restrict__ out) {
    const int b = blockIdx.y;
    const int o = blockIdx.x * 256 + threadIdx.x;
    __shared__ float sg[512];
    for (int i = threadIdx.x; i < 512; i += 256) sg[i] = gmax[(size_t)b * 512 + i];
    __syncthreads();
    const float* wrow = lw + (size_t)o * 512;
    double acc = 0.0;
#pragma unroll 8
    for (int c = 0; c < 512; ++c) acc += (double)sg[c] * (double)wrow[c];
    acc += (double)lb[o];
    const double scale = (double)g5[o] / sqrt((double)rv5[o] + 1e-5);
    double h = (acc - (double)rm5[o]) * scale + (double)b5[o];
    float hf = (float)h;
    out[(size_t)b * 1024 + o] = hf >= 0.f ? hf : 0.2f * hf;
}

// ---------------- launch ----------------
extern "C" void kernel_launch(void* const* d_in, const int* in_sizes, int n_in,
                              void* d_out, int out_size) {
    const float* x    = (const float*)d_in[0];
    const float* w1   = (const float*)d_in[1];
    const float* g1   = (const float*)d_in[2];
    const float* b1   = (const float*)d_in[3];
    const float* rm1  = (const float*)d_in[4];
    const float* rv1  = (const float*)d_in[5];
    const float* w2   = (const float*)d_in[6];
    const float* g2   = (const float*)d_in[7];
    const float* b2   = (const float*)d_in[8];
    const float* rm2  = (const float*)d_in[9];
    const float* rv2  = (const float*)d_in[10];
    const float* w3   = (const float*)d_in[11];
    const float* g3   = (const float*)d_in[12];
    const float* b3   = (const float*)d_in[13];
    const float* rm3  = (const float*)d_in[14];
    const float* rv3  = (const float*)d_in[15];
    const float* w4   = (const float*)d_in[16];
    const float* g4   = (const float*)d_in[17];
    const float* b4   = (const float*)d_in[18];
    const float* rm4  = (const float*)d_in[19];
    const float* rv4  = (const float*)d_in[20];
    const float* lw   = (const float*)d_in[21];
    const float* lb   = (const float*)d_in[22];
    const float* g5   = (const float*)d_in[23];
    const float* b5   = (const float*)d_in[24];
    const float* rm5  = (const float*)d_in[25];
    const float* rv5  = (const float*)d_in[26];

    float *x1, *x2, *x3, *x4, *yz, *wp, *part, *gmax, *dist, *nrmf;
    int *idx, *cand;
    double* nrm;
    cudaGetSymbolAddress((void**)&x1, d_x1);
    cudaGetSymbolAddress((void**)&x2, d_x2);
    cudaGetSymbolAddress((void**)&x3, d_x3);
    cudaGetSymbolAddress((void**)&x4, d_x4);
    cudaGetSymbolAddress((void**)&yz, d_yz);
    cudaGetSymbolAddress((void**)&dist, d_dist);
    cudaGetSymbolAddress((void**)&idx, d_idxbuf);
    cudaGetSymbolAddress((void**)&cand, d_cand);
    cudaGetSymbolAddress((void**)&nrm, d_norm);
    cudaGetSymbolAddress((void**)&nrmf, d_normf);
    cudaGetSymbolAddress((void**)&wp, d_wp);
    cudaGetSymbolAddress((void**)&part, d_part);
    cudaGetSymbolAddress((void**)&gmax, d_gmax);

    float* out = (float*)d_out;
    float* x4T = out + B_ * 1024;

    const dim3 dist_grid(NPTS / 128, NPTS / 128, B_);
    const int nrm_blocks = (MTOT * 32 + 255) / 256;
    const int sel_blocks = MTOT / 8;
    const int rr_blocks = MTOT / 8;

    // layer 1: C=5 -> O=64   (select16 at capture slot #4 to measure the prefilter)
    compute_norms<5><<<nrm_blocks, 256>>>(x, nrm, nrmf);
    prep_w<<<(64 * 5 + 255) / 256, 256>>>(w1, wp, 64, 5);
    gemm128<5, true><<<dist_grid, 256>>>(x, nullptr, nrmf, dist, NPTS);
    select16<<<sel_blocks, 256>>>(dist, cand);
    gemm128<5, false><<<dim3(1, MTOT / 128, 1), 256>>>(x, wp, nullptr, yz, 128);
    rerank<5><<<rr_blocks, 256>>>(x, nrm, cand, idx);
    edge_reduce<<<MTOT, 64>>>(yz, idx, g1, b1, rm1, rv1, x1, 64);

    // layer 2: C=64 -> O=64
    compute_norms<64><<<nrm_blocks, 256>>>(x1, nrm, nrmf);
    prep_w<<<(64 * 64 + 255) / 256, 256>>>(w2, wp, 64, 64);
    gemm128<64, true><<<dist_grid, 256>>>(x1, nullptr, nrmf, dist, NPTS);
    select16<<<sel_blocks, 256>>>(dist, cand);
    gemm128<64, false><<<dim3(1, MTOT / 128, 1), 256>>>(x1, wp, nullptr, yz, 128);
    rerank<64><<<rr_blocks, 256>>>(x1, nrm, cand, idx);
    edge_reduce<<<MTOT, 64>>>(yz, idx, g2, b2, rm2, rv2, x2, 64);

    // layer 3: C=64 -> O=128
    compute_norms<64><<<nrm_blocks, 256>>>(x2, nrm, nrmf);
    prep_w<<<(128 * 64 + 255) / 256, 256>>>(w3, wp, 128, 64);
    gemm128<64, true><<<dist_grid, 256>>>(x2, nullptr, nrmf, dist, NPTS);
    select16<<<sel_blocks, 256>>>(dist, cand);
    gemm128<64, false><<<dim3(2, MTOT / 128, 1), 256>>>(x2, wp, nullptr, yz, 256);
    rerank<64><<<rr_blocks, 256>>>(x2, nrm, cand, idx);
    edge_reduce<<<MTOT, 128>>>(yz, idx, g3, b3, rm3, rv3, x3, 128);

    // layer 4: C=128 -> O=256
    compute_norms<128><<<nrm_blocks, 256>>>(x3, nrm, nrmf);
    prep_w<<<(256 * 128 + 255) / 256, 256>>>(w4, wp, 256, 128);
    gemm128<128, true><<<dist_grid, 256>>>(x3, nullptr, nrmf, dist, NPTS);
    select16<<<sel_blocks, 256>>>(dist, cand);
    gemm128<128, false><<<dim3(4, MTOT / 128, 1), 256>>>(x3, wp, nullptr, yz, 512);
    rerank<128><<<rr_blocks, 256>>>(x3, nrm, cand, idx);
    edge_reduce<<<MTOT, 256>>>(yz, idx, g4, b4, rm4, rv4, x4, 256);
    transpose_x4<<<dim3(NPTS / 32, 256 / 32, B_), dim3(32, 8)>>>(x4, x4T);

    // global max + final FC
    gmax_partial<<<dim3(B_, 16), 512>>>(x1, x2, x3, x4, part);
    gmax_final<<<B_, 512>>>(part, gmax);
    final_fc<<<dim3(4, B_), 256>>>(gmax, lw, lb, g5, b5, rm5, rv5, out);
}

// round 16
// speedup vs baseline: 1.2476x; 1.0591x over previous
#include <cuda_runtime.h>
#include <math.h>

#define B_ 8
#define NPTS 2048
#define KNB 10
#define KSEL 16
#define EPSV 1e-5f
#define MTOT (B_ * NPTS)

// ---------------- scratch (no allocation allowed) ----------------
__device__ float  d_x1[MTOT * 64];
__device__ float  d_x2[MTOT * 64];
__device__ float  d_x3[MTOT * 128];
__device__ float  d_x4[MTOT * 256];
__device__ float  d_yz[MTOT * 512];
__device__ float  d_dist[(size_t)MTOT * NPTS];   // 134 MB ranking scores
__device__ int    d_idxbuf[MTOT * KNB];
__device__ int    d_cand[MTOT * KSEL];
__device__ double d_norm[MTOT];
__device__ float  d_normf[MTOT];
__device__ float  d_wp[512 * 128];
__device__ float  d_part[B_ * 16 * 512];
__device__ float  d_gmax[B_ * 512];

// ---------------- helpers ----------------
__device__ __forceinline__ void ins4(float v[4], int id[4], float d, int m) {
    if (d > v[3]) {
        float cv = d; int ci = m;
#pragma unroll
        for (int p = 0; p < 4; ++p) {
            if (cv > v[p]) {
                float t = v[p]; v[p] = cv; cv = t;
                int u = id[p]; id[p] = ci; ci = u;
            }
        }
    }
}

// ---------------- point norms: one warp per point; fp64 (rerank) + fp32 (pass-1) ----------------
template <int C>
__global__ void compute_norms(const float* __restrict__ x, double* __restrict__ nrm,
                              float* __restrict__ nrmf) {
    const unsigned FULL = 0xffffffffu;
    const int gw = (blockIdx.x * 256 + threadIdx.x) >> 5;
    const int lane = threadIdx.x & 31;
    if (gw >= MTOT) return;
    const float* p = x + (size_t)gw * C;
    double s = 0.0;
#pragma unroll
    for (int c = lane; c < C; c += 32) { double v = (double)p[c]; s += v * v; }
#pragma unroll
    for (int off = 16; off; off >>= 1) s += __shfl_down_sync(FULL, s, off);
    if (lane == 0) { nrm[gw] = s; nrmf[gw] = (float)s; }
}

// ---------------- 128x128 tile GEMM, 8x8 microtile, 256 threads (plain FFMA, R10-proven) ----
// DIST=true : Y[(bz*NPTS + n)*NPTS + m] = 2*<x_n, x_m> - ||x_m||^2  (grid (16,16,B))
// DIST=false: Y[n*N + m] = <X_n, W_m>                                (grid (N/128, MTOT/128, 1))
template <int K, bool DIST>
__global__ void __launch_bounds__(256)
gemm128(const float* __restrict__ A, const float* __restrict__ Bw,
        const float* __restrict__ nf, float* __restrict__ Y, int N) {
    __shared__ float sA[16][132];
    __shared__ float sB[16][132];
    const int bz = blockIdx.z;
    const float* Ab = A + (DIST ? (size_t)bz * NPTS * K : (size_t)0);
    const float* Bb = DIST ? Ab : Bw;
    const int rt0 = blockIdx.y * 128;   // output rows (n)
    const int ct0 = blockIdx.x * 128;   // output cols (m)
    const int tid = threadIdx.x;
    const int tx = tid & 15, ty = tid >> 4;

    float acc[8][8] = {};

    for (int kt = 0; kt < K; kt += 16) {
        if (K % 4 == 0) {
#pragma unroll
            for (int i = tid; i < 512; i += 256) {
                int r = i >> 2, kq = (i & 3) << 2;
                int kg = kt + kq;
                float4 t = make_float4(0.f, 0.f, 0.f, 0.f);
                float4 u = make_float4(0.f, 0.f, 0.f, 0.f);
                if (kg < K) {
                    t = *(const float4*)&Ab[(size_t)(rt0 + r) * K + kg];
                    u = *(const float4*)&Bb[(size_t)(ct0 + r) * K + kg];
                }
                sA[kq + 0][r] = t.x; sA[kq + 1][r] = t.y;
                sA[kq + 2][r] = t.z; sA[kq + 3][r] = t.w;
                sB[kq + 0][r] = u.x; sB[kq + 1][r] = u.y;
                sB[kq + 2][r] = u.z; sB[kq + 3][r] = u.w;
            }
        } else {
            for (int i = tid; i < 2048; i += 256) {
                int r = i >> 4, k = i & 15;
                int kg = kt + k;
                sA[k][r] = (kg < K) ? Ab[(size_t)(rt0 + r) * K + kg] : 0.f;
                sB[k][r] = (kg < K) ? Bb[(size_t)(ct0 + r) * K + kg] : 0.f;
            }
        }
        __syncthreads();
#pragma unroll
        for (int kk = 0; kk < 16; ++kk) {
            float a[8], bb[8];
            *(float4*)&a[0]  = *(const float4*)&sA[kk][ty * 8];
            *(float4*)&a[4]  = *(const float4*)&sA[kk][ty * 8 + 4];
            *(float4*)&bb[0] = *(const float4*)&sB[kk][tx * 8];
            *(float4*)&bb[4] = *(const float4*)&sB[kk][tx * 8 + 4];
#pragma unroll
            for (int i2 = 0; i2 < 8; ++i2)
#pragma unroll
                for (int j2 = 0; j2 < 8; ++j2)
                    acc[i2][j2] += a[i2] * bb[j2];
        }
        __syncthreads();
    }

    if (DIST) {
        const float* nfb = nf + (size_t)bz * NPTS;
        float nmv[8];
        *(float4*)&nmv[0] = *(const float4*)&nfb[ct0 + tx * 8];
        *(float4*)&nmv[4] = *(const float4*)&nfb[ct0 + tx * 8 + 4];
#pragma unroll
        for (int i2 = 0; i2 < 8; ++i2) {
            float4 o0, o1;
            o0.x = 2.f * acc[i2][0] - nmv[0]; o0.y = 2.f * acc[i2][1] - nmv[1];
            o0.z = 2.f * acc[i2][2] - nmv[2]; o0.w = 2.f * acc[i2][3] - nmv[3];
            o1.x = 2.f * acc[i2][4] - nmv[4]; o1.y = 2.f * acc[i2][5] - nmv[5];
            o1.z = 2.f * acc[i2][6] - nmv[6]; o1.w = 2.f * acc[i2][7] - nmv[7];
            float* dst = Y + ((size_t)bz * NPTS + rt0 + ty * 8 + i2) * NPTS + ct0 + tx * 8;
            *(float4*)&dst[0] = o0;
            *(float4*)&dst[4] = o1;
        }
    } else {
#pragma unroll
        for (int i2 = 0; i2 < 8; ++i2) {
            float* dst = Y + (size_t)(rt0 + ty * 8 + i2) * N + ct0 + tx * 8;
            *(float4*)&dst[0] = make_float4(acc[i2][0], acc[i2][1], acc[i2][2], acc[i2][3]);
            *(float4*)&dst[4] = make_float4(acc[i2][4], acc[i2][5], acc[i2][6], acc[i2][7]);
        }
    }
}

// ---------------- selection: warp per row; float4 loads, top-4 cache + pops + exact rescan ----
// (R12 variant, measured 86.3us; no prefilter)
__global__ void __launch_bounds__(256)
select16(const float* __restrict__ D, int* __restrict__ cand) {
    const unsigned FULL = 0xffffffffu;
    const int warp = threadIdx.x >> 5, lane = threadIdx.x & 31;
    const int point = blockIdx.x * 8 + warp;   // global b*NPTS+n
    const float4* rowv = (const float4*)(D + (size_t)point * NPTS);

    float v[4]; int id[4];
#pragma unroll
    for (int q = 0; q < 4; ++q) { v[q] = -INFINITY; id[q] = 0x7fffffff; }

#pragma unroll
    for (int t = 0; t < NPTS / 128; ++t) {
        float4 qv = rowv[t * 32 + lane];
        const int base = (t * 32 + lane) * 4;
        ins4(v, id, qv.x, base);
        ins4(v, id, qv.y, base + 1);
        ins4(v, id, qv.z, base + 2);
        ins4(v, id, qv.w, base + 3);
    }

    int em[KSEL];
    int* out = cand + (size_t)point * KSEL;
#pragma unroll 1
    for (int r = 0; r < KSEL; ++r) {
        if (v[0] == -INFINITY) {
            // cache exhausted for this lane: exact refill excluding emitted ids
            for (int t = 0; t < NPTS / 128; ++t) {
                float4 qv = rowv[t * 32 + lane];
                const int base = (t * 32 + lane) * 4;
                float qq[4] = {qv.x, qv.y, qv.z, qv.w};
#pragma unroll
                for (int j = 0; j < 4; ++j) {
                    const int m = base + j;
                    bool skip = false;
                    for (int e = 0; e < r; ++e) skip |= (em[e] == m);
                    if (!skip) ins4(v, id, qq[j], m);
                }
            }
        }
        float vv = v[0]; int ii = id[0];
#pragma unroll
        for (int off = 16; off; off >>= 1) {
            float ov = __shfl_down_sync(FULL, vv, off);
            int   oi = __shfl_down_sync(FULL, ii, off);
            if (ov > vv || (ov == vv && oi < ii)) { vv = ov; ii = oi; }
        }
        const int bi = __shfl_sync(FULL, ii, 0);
        em[r] = bi;
        if (lane == 0) out[r] = bi;
        if (id[0] == bi) {   // owner lane pops (indices unique per lane)
#pragma unroll
            for (int q = 0; q < 3; ++q) { v[q] = v[q + 1]; id[q] = id[q + 1]; }
            v[3] = -INFINITY; id[3] = 0x7fffffff;
        }
    }
}

// ---------------- kNN pass 2: fp64 exact rescore of top-16, keep true top-10 ----------------
template <int C>
__global__ void rerank(const float* __restrict__ x, const double* __restrict__ nrm,
                       const int* __restrict__ cand, int* __restrict__ idxout) {
    const unsigned FULL = 0xffffffffu;
    __shared__ float s_cent[8][C];
    const int warp = threadIdx.x >> 5, lane = threadIdx.x & 31;
    const int point = blockIdx.x * 8 + warp;          // global b*NPTS+n
    const int browbase = point & ~(NPTS - 1);
    const float* xb = x + (size_t)browbase * C;
    const int nloc = point - browbase;

    for (int c = lane; c < C; c += 32) s_cent[warp][c] = xb[(size_t)nloc * C + c];
    __syncwarp();

    double d = -INFINITY;
    int mi = 0x7fffffff;
    if (lane < KSEL) {
        mi = cand[(size_t)point * KSEL + lane];
        const float* row = xb + (size_t)mi * C;
        if (C % 4 == 0) {
            double a0 = 0.0, a1 = 0.0, a2 = 0.0, a3 = 0.0;
#pragma unroll
            for (int c = 0; c < C; c += 4) {
                float4 r = *(const float4*)&row[c];
                a0 += (double)s_cent[warp][c + 0] * (double)r.x;
                a1 += (double)s_cent[warp][c + 1] * (double)r.y;
                a2 += (double)s_cent[warp][c + 2] * (double)r.z;
                a3 += (double)s_cent[warp][c + 3] * (double)r.w;
            }
            d = 2.0 * ((a0 + a1) + (a2 + a3)) - nrm[point] - nrm[browbase + mi];
        } else {
            double dot = 0.0;
#pragma unroll
            for (int c = 0; c < C; ++c)
                dot += (double)s_cent[warp][c] * (double)row[c];
            d = 2.0 * dot - nrm[point] - nrm[browbase + mi];
        }
    }

    int* out = idxout + (size_t)point * KNB;
#pragma unroll
    for (int r = 0; r < KNB; ++r) {
        double v = d; int i_ = mi;
#pragma unroll
        for (int off = 16; off; off >>= 1) {
            double ov = __shfl_down_sync(FULL, v, off);
            int    oi = __shfl_down_sync(FULL, i_, off);
            if (ov > v || (ov == v && oi < i_)) { v = ov; i_ = oi; }
        }
        double bv = __shfl_sync(FULL, v, 0);
        int    bi = __shfl_sync(FULL, i_, 0);
        if (lane == 0) out[r] = bi;
        if (d == bv && mi == bi) d = -INFINITY;
    }
}

// ---------------- weight prep: Wp = [A ; B - A] ----------------
__global__ void prep_w(const float* __restrict__ w, float* __restrict__ wp, int O, int C) {
    int i = blockIdx.x * 256 + threadIdx.x;
    if (i < O * C) {
        int o = i / C, c = i % C;
        float a = w[(size_t)o * 2 * C + c];
        wp[i] = a;
        wp[(size_t)O * C + i] = w[(size_t)o * 2 * C + C + c] - a;
    }
}

// ---------------- gather + reduce + BN + lrelu: 256/O points per 256-thread block ----------
template <int O>
__global__ void __launch_bounds__(256)
edge_reduce(const float* __restrict__ yz, const int* __restrict__ idx,
            const float* __restrict__ gg, const float* __restrict__ bb,
            const float* __restrict__ rm, const float* __restrict__ rv,
            float* __restrict__ xout) {
    constexpr int PPB = 256 / O;
    const int pl = threadIdx.x / O;        // local point 0..PPB-1
    const int o  = threadIdx.x % O;
    const int bn = blockIdx.x * PPB + pl;  // global b*NPTS+n
    const int b = bn >> 11;
    __shared__ int sj[PPB][KNB];
    if (o < KNB) sj[pl][o] = idx[(size_t)bn * KNB + o];
    __syncthreads();
    const double scale = (double)gg[o] / sqrt((double)rv[o] + 1e-5);
    const int twoO = 2 * O;
    const float z = yz[(size_t)bn * twoO + O + o];
    const int browbase = b << 11;
    float red;
    if (scale >= 0.0) {
        red = -INFINITY;
#pragma unroll
        for (int j = 0; j < KNB; ++j)
            red = fmaxf(red, yz[(size_t)(browbase + sj[pl][j]) * twoO + o]);
    } else {
        red = INFINITY;
#pragma unroll
        for (int j = 0; j < KNB; ++j)
            red = fminf(red, yz[(size_t)(browbase + sj[pl][j]) * twoO + o]);
    }
    double h = (((double)red + (double)z) - (double)rm[o]) * scale + (double)bb[o];
    float hf = (float)h;
    float r = hf >= 0.f ? hf : 0.2f * hf;
    xout[(size_t)bn * O + o] = r;
}

// ---------------- tiled transpose: x4 [B*NPTS,256] -> outT [B,256,NPTS] ----------------
__global__ void transpose_x4(const float* __restrict__ src, float* __restrict__ dst) {
    __shared__ float t[32][33];
    const int b = blockIdx.z;
    const int n0 = blockIdx.x * 32, o0 = blockIdx.y * 32;
    const int lx = threadIdx.x, ly = threadIdx.y;
    for (int i = ly; i < 32; i += 8)
        t[i][lx] = src[((size_t)(b * NPTS + n0 + i)) * 256 + o0 + lx];
    __syncthreads();
    for (int i = ly; i < 32; i += 8)
        dst[((size_t)(b * 256 + o0 + i)) * NPTS + n0 + lx] = t[lx][i];
}

// ---------------- global max (two pass) ----------------
__global__ void gmax_partial(const float* __restrict__ x1, const float* __restrict__ x2,
                             const float* __restrict__ x3, const float* __restrict__ x4,
                             float* __restrict__ part) {
    const int b = blockIdx.x, chunk = blockIdx.y;
    const int c = threadIdx.x;  // 0..511
    const float* src; int O, off;
    if (c < 64)       { src = x1; O = 64;  off = c; }
    else if (c < 128) { src = x2; O = 64;  off = c - 64; }
    else if (c < 256) { src = x3; O = 128; off = c - 128; }
    else              { src = x4; O = 256; off = c - 256; }
    float m = -INFINITY;
    const int nbeg = chunk * 128;
    const float* p = src + ((size_t)b * NPTS + nbeg) * O + off;
    for (int n = 0; n < 128; ++n) m = fmaxf(m, p[(size_t)n * O]);
    part[((size_t)b * 16 + chunk) * 512 + c] = m;
}

__global__ void gmax_final(const float* __restrict__ part, float* __restrict__ gmax) {
    const int b = blockIdx.x, c = threadIdx.x;
    float m = -INFINITY;
    for (int ch = 0; ch < 16; ++ch)
        m = fmaxf(m, part[((size_t)b * 16 + ch) * 512 + c]);
    gmax[(size_t)b * 512 + c] = m;
}

// ---------------- final FC + BN + lrelu (fp64 accumulate) ----------------
__global__ void final_fc(const float* __restrict__ gmax, const float* __restrict__ lw,
                         const float* __restrict__ lb, const float* __restrict__ g5,
                         const float* __restrict__ b5, const float* __restrict__ rm5,
                         const float* __restrict__ rv5, float* __restrict__ out) {
    const int b = blockIdx.y;
    const int o = blockIdx.x * 256 + threadIdx.x;
    __shared__ float sg[512];
    for (int i = threadIdx.x; i < 512; i += 256) sg[i] = gmax[(size_t)b * 512 + i];
    __syncthreads();
    const float* wrow = lw + (size_t)o * 512;
    double acc = 0.0;
#pragma unroll 8
    for (int c = 0; c < 512; ++c) acc += (double)sg[c] * (double)wrow[c];
    acc += (double)lb[o];
    const double scale = (double)g5[o] / sqrt((double)rv5[o] + 1e-5);
    double h = (acc - (double)rm5[o]) * scale + (double)b5[o];
    float hf = (float)h;
    out[(size_t)b * 1024 + o] = hf >= 0.f ? hf : 0.2f * hf;
}

// ---------------- launch ----------------
extern "C" void kernel_launch(void* const* d_in, const int* in_sizes, int n_in,
                              void* d_out, int out_size) {
    const float* x    = (const float*)d_in[0];
    const float* w1   = (const float*)d_in[1];
    const float* g1   = (const float*)d_in[2];
    const float* b1   = (const float*)d_in[3];
    const float* rm1  = (const float*)d_in[4];
    const float* rv1  = (const float*)d_in[5];
    const float* w2   = (const float*)d_in[6];
    const float* g2   = (const float*)d_in[7];
    const float* b2   = (const float*)d_in[8];
    const float* rm2  = (const float*)d_in[9];
    const float* rv2  = (const float*)d_in[10];
    const float* w3   = (const float*)d_in[11];
    const float* g3   = (const float*)d_in[12];
    const float* b3   = (const float*)d_in[13];
    const float* rm3  = (const float*)d_in[14];
    const float* rv3  = (const float*)d_in[15];
    const float* w4   = (const float*)d_in[16];
    const float* g4   = (const float*)d_in[17];
    const float* b4   = (const float*)d_in[18];
    const float* rm4  = (const float*)d_in[19];
    const float* rv4  = (const float*)d_in[20];
    const float* lw   = (const float*)d_in[21];
    const float* lb   = (const float*)d_in[22];
    const float* g5   = (const float*)d_in[23];
    const float* b5   = (const float*)d_in[24];
    const float* rm5  = (const float*)d_in[25];
    const float* rv5  = (const float*)d_in[26];

    float *x1, *x2, *x3, *x4, *yz, *wp, *part, *gmax, *dist, *nrmf;
    int *idx, *cand;
    double* nrm;
    cudaGetSymbolAddress((void**)&x1, d_x1);
    cudaGetSymbolAddress((void**)&x2, d_x2);
    cudaGetSymbolAddress((void**)&x3, d_x3);
    cudaGetSymbolAddress((void**)&x4, d_x4);
    cudaGetSymbolAddress((void**)&yz, d_yz);
    cudaGetSymbolAddress((void**)&dist, d_dist);
    cudaGetSymbolAddress((void**)&idx, d_idxbuf);
    cudaGetSymbolAddress((void**)&cand, d_cand);
    cudaGetSymbolAddress((void**)&nrm, d_norm);
    cudaGetSymbolAddress((void**)&nrmf, d_normf);
    cudaGetSymbolAddress((void**)&wp, d_wp);
    cudaGetSymbolAddress((void**)&part, d_part);
    cudaGetSymbolAddress((void**)&gmax, d_gmax);

    float* out = (float*)d_out;
    float* x4T = out + B_ * 1024;

    const dim3 dist_grid(NPTS / 128, NPTS / 128, B_);
    const int nrm_blocks = (MTOT * 32 + 255) / 256;
    const int sel_blocks = MTOT / 8;
    const int rr_blocks = MTOT / 8;

    // layer 1: C=5 -> O=64   (rerank<5> at capture slot #4)
    compute_norms<5><<<nrm_blocks, 256>>>(x, nrm, nrmf);
    gemm128<5, true><<<dist_grid, 256>>>(x, nullptr, nrmf, dist, NPTS);
    select16<<<sel_blocks, 256>>>(dist, cand);
    rerank<5><<<rr_blocks, 256>>>(x, nrm, cand, idx);
    prep_w<<<(64 * 5 + 255) / 256, 256>>>(w1, wp, 64, 5);
    gemm128<5, false><<<dim3(1, MTOT / 128, 1), 256>>>(x, wp, nullptr, yz, 128);
    edge_reduce<64><<<MTOT / 4, 256>>>(yz, idx, g1, b1, rm1, rv1, x1);

    // layer 2: C=64 -> O=64
    compute_norms<64><<<nrm_blocks, 256>>>(x1, nrm, nrmf);
    gemm128<64, true><<<dist_grid, 256>>>(x1, nullptr, nrmf, dist, NPTS);
    select16<<<sel_blocks, 256>>>(dist, cand);
    rerank<64><<<rr_blocks, 256>>>(x1, nrm, cand, idx);
    prep_w<<<(64 * 64 + 255) / 256, 256>>>(w2, wp, 64, 64);
    gemm128<64, false><<<dim3(1, MTOT / 128, 1), 256>>>(x1, wp, nullptr, yz, 128);
    edge_reduce<64><<<MTOT / 4, 256>>>(yz, idx, g2, b2, rm2, rv2, x2);

    // layer 3: C=64 -> O=128
    compute_norms<64><<<nrm_blocks, 256>>>(x2, nrm, nrmf);
    gemm128<64, true><<<dist_grid, 256>>>(x2, nullptr, nrmf, dist, NPTS);
    select16<<<sel_blocks, 256>>>(dist, cand);
    rerank<64><<<rr_blocks, 256>>>(x2, nrm, cand, idx);
    prep_w<<<(128 * 64 + 255) / 256, 256>>>(w3, wp, 128, 64);
    gemm128<64, false><<<dim3(2, MTOT / 128, 1), 256>>>(x2, wp, nullptr, yz, 256);
    edge_reduce<128><<<MTOT / 2, 256>>>(yz, idx, g3, b3, rm3, rv3, x3);

    // layer 4: C=128 -> O=256
    compute_norms<128><<<nrm_blocks, 256>>>(x3, nrm, nrmf);
    gemm128<128, true><<<dist_grid, 256>>>(x3, nullptr, nrmf, dist, NPTS);
    select16<<<sel_blocks, 256>>>(dist, cand);
    rerank<128><<<rr_blocks, 256>>>(x3, nrm, cand, idx);
    prep_w<<<(256 * 128 + 255) / 256, 256>>>(w4, wp, 256, 128);
    gemm128<128, false><<<dim3(4, MTOT / 128, 1), 256>>>(x3, wp, nullptr, yz, 512);
    edge_reduce<256><<<MTOT, 256>>>(yz, idx, g4, b4, rm4, rv4, x4);
    transpose_x4<<<dim3(NPTS / 32, 256 / 32, B_), dim3(32, 8)>>>(x4, x4T);

    // global max + final FC
    gmax_partial<<<dim3(B_, 16), 512>>>(x1, x2, x3, x4, part);
    gmax_final<<<B_, 512>>>(part, gmax);
    final_fc<<<dim3(4, B_), 256>>>(gmax, lw, lb, g5, b5, rm5, rv5, out);
}

// round 17
// speedup vs baseline: 1.4119x; 1.1318x over previous
#include <cuda_runtime.h>
#include <math.h>

#define B_ 8
#define NPTS 2048
#define KNB 10
#define KSEL 16
#define EPSV 1e-5f
#define MTOT (B_ * NPTS)

// ---------------- scratch (no allocation allowed) ----------------
__device__ float  d_x1[MTOT * 64];
__device__ float  d_x2[MTOT * 64];
__device__ float  d_x3[MTOT * 128];
__device__ float  d_x4[MTOT * 256];
__device__ float  d_yz[MTOT * 512];
__device__ float  d_dist[(size_t)MTOT * NPTS];   // 134 MB ranking scores
__device__ int    d_idxbuf[MTOT * KNB];
__device__ int    d_cand[MTOT * KSEL];
__device__ double d_norm[MTOT];
__device__ float  d_normf[MTOT];
__device__ float  d_wp[512 * 128];
__device__ float  d_part[B_ * 16 * 512];
__device__ float  d_gmax[B_ * 512];

// ---------------- helpers ----------------
__device__ __forceinline__ void ins4(float v[4], int id[4], float d, int m) {
    if (d > v[3]) {
        float cv = d; int ci = m;
#pragma unroll
        for (int p = 0; p < 4; ++p) {
            if (cv > v[p]) {
                float t = v[p]; v[p] = cv; cv = t;
                int u = id[p]; id[p] = ci; ci = u;
            }
        }
    }
}

// ---------------- point norms: one warp per point; fp64 (rerank) + fp32 (pass-1) ----------------
template <int C>
__global__ void compute_norms(const float* __restrict__ x, double* __restrict__ nrm,
                              float* __restrict__ nrmf) {
    const unsigned FULL = 0xffffffffu;
    const int gw = (blockIdx.x * 256 + threadIdx.x) >> 5;
    const int lane = threadIdx.x & 31;
    if (gw >= MTOT) return;
    const float* p = x + (size_t)gw * C;
    double s = 0.0;
#pragma unroll
    for (int c = lane; c < C; c += 32) { double v = (double)p[c]; s += v * v; }
#pragma unroll
    for (int off = 16; off; off >>= 1) s += __shfl_down_sync(FULL, s, off);
    if (lane == 0) { nrm[gw] = s; nrmf[gw] = (float)s; }
}

// ---------------- 128x128 tile GEMM, 8x8 microtile, 256 threads (plain FFMA, R10-proven) ----
// DIST=true : Y[(bz*NPTS + n)*NPTS + m] = 2*<x_n, x_m> - ||x_m||^2  (grid (16,16,B))
// DIST=false: Y[n*N + m] = <X_n, W_m>                                (grid (N/128, MTOT/128, 1))
template <int K, bool DIST>
__global__ void __launch_bounds__(256)
gemm128(const float* __restrict__ A, const float* __restrict__ Bw,
        const float* __restrict__ nf, float* __restrict__ Y, int N) {
    __shared__ float sA[16][132];
    __shared__ float sB[16][132];
    const int bz = blockIdx.z;
    const float* Ab = A + (DIST ? (size_t)bz * NPTS * K : (size_t)0);
    const float* Bb = DIST ? Ab : Bw;
    const int rt0 = blockIdx.y * 128;   // output rows (n)
    const int ct0 = blockIdx.x * 128;   // output cols (m)
    const int tid = threadIdx.x;
    const int tx = tid & 15, ty = tid >> 4;

    float acc[8][8] = {};

    for (int kt = 0; kt < K; kt += 16) {
        if (K % 4 == 0) {
#pragma unroll
            for (int i = tid; i < 512; i += 256) {
                int r = i >> 2, kq = (i & 3) << 2;
                int kg = kt + kq;
                float4 t = make_float4(0.f, 0.f, 0.f, 0.f);
                float4 u = make_float4(0.f, 0.f, 0.f, 0.f);
                if (kg < K) {
                    t = *(const float4*)&Ab[(size_t)(rt0 + r) * K + kg];
                    u = *(const float4*)&Bb[(size_t)(ct0 + r) * K + kg];
                }
                sA[kq + 0][r] = t.x; sA[kq + 1][r] = t.y;
                sA[kq + 2][r] = t.z; sA[kq + 3][r] = t.w;
                sB[kq + 0][r] = u.x; sB[kq + 1][r] = u.y;
                sB[kq + 2][r] = u.z; sB[kq + 3][r] = u.w;
            }
        } else {
            for (int i = tid; i < 2048; i += 256) {
                int r = i >> 4, k = i & 15;
                int kg = kt + k;
                sA[k][r] = (kg < K) ? Ab[(size_t)(rt0 + r) * K + kg] : 0.f;
                sB[k][r] = (kg < K) ? Bb[(size_t)(ct0 + r) * K + kg] : 0.f;
            }
        }
        __syncthreads();
#pragma unroll
        for (int kk = 0; kk < 16; ++kk) {
            float a[8], bb[8];
            *(float4*)&a[0]  = *(const float4*)&sA[kk][ty * 8];
            *(float4*)&a[4]  = *(const float4*)&sA[kk][ty * 8 + 4];
            *(float4*)&bb[0] = *(const float4*)&sB[kk][tx * 8];
            *(float4*)&bb[4] = *(const float4*)&sB[kk][tx * 8 + 4];
#pragma unroll
            for (int i2 = 0; i2 < 8; ++i2)
#pragma unroll
                for (int j2 = 0; j2 < 8; ++j2)
                    acc[i2][j2] += a[i2] * bb[j2];
        }
        __syncthreads();
    }

    if (DIST) {
        const float* nfb = nf + (size_t)bz * NPTS;
        float nmv[8];
        *(float4*)&nmv[0] = *(const float4*)&nfb[ct0 + tx * 8];
        *(float4*)&nmv[4] = *(const float4*)&nfb[ct0 + tx * 8 + 4];
#pragma unroll
        for (int i2 = 0; i2 < 8; ++i2) {
            float4 o0, o1;
            o0.x = 2.f * acc[i2][0] - nmv[0]; o0.y = 2.f * acc[i2][1] - nmv[1];
            o0.z = 2.f * acc[i2][2] - nmv[2]; o0.w = 2.f * acc[i2][3] - nmv[3];
            o1.x = 2.f * acc[i2][4] - nmv[4]; o1.y = 2.f * acc[i2][5] - nmv[5];
            o1.z = 2.f * acc[i2][6] - nmv[6]; o1.w = 2.f * acc[i2][7] - nmv[7];
            float* dst = Y + ((size_t)bz * NPTS + rt0 + ty * 8 + i2) * NPTS + ct0 + tx * 8;
            *(float4*)&dst[0] = o0;
            *(float4*)&dst[4] = o1;
        }
    } else {
#pragma unroll
        for (int i2 = 0; i2 < 8; ++i2) {
            float* dst = Y + (size_t)(rt0 + ty * 8 + i2) * N + ct0 + tx * 8;
            *(float4*)&dst[0] = make_float4(acc[i2][0], acc[i2][1], acc[i2][2], acc[i2][3]);
            *(float4*)&dst[4] = make_float4(acc[i2][4], acc[i2][5], acc[i2][6], acc[i2][7]);
        }
    }
}

// ---------------- selection: warp per row; float4 loads, top-4 cache + pops + exact rescan ----
__global__ void __launch_bounds__(256)
select16(const float* __restrict__ D, int* __restrict__ cand) {
    const unsigned FULL = 0xffffffffu;
    const int warp = threadIdx.x >> 5, lane = threadIdx.x & 31;
    const int point = blockIdx.x * 8 + warp;   // global b*NPTS+n
    const float4* rowv = (const float4*)(D + (size_t)point * NPTS);

    float v[4]; int id[4];
#pragma unroll
    for (int q = 0; q < 4; ++q) { v[q] = -INFINITY; id[q] = 0x7fffffff; }

#pragma unroll
    for (int t = 0; t < NPTS / 128; ++t) {
        float4 qv = rowv[t * 32 + lane];
        const int base = (t * 32 + lane) * 4;
        ins4(v, id, qv.x, base);
        ins4(v, id, qv.y, base + 1);
        ins4(v, id, qv.z, base + 2);
        ins4(v, id, qv.w, base + 3);
    }

    int em[KSEL];
    int* out = cand + (size_t)point * KSEL;
#pragma unroll 1
    for (int r = 0; r < KSEL; ++r) {
        if (v[0] == -INFINITY) {
            // cache exhausted for this lane: exact refill excluding emitted ids
            for (int t = 0; t < NPTS / 128; ++t) {
                float4 qv = rowv[t * 32 + lane];
                const int base = (t * 32 + lane) * 4;
                float qq[4] = {qv.x, qv.y, qv.z, qv.w};
#pragma unroll
                for (int j = 0; j < 4; ++j) {
                    const int m = base + j;
                    bool skip = false;
                    for (int e = 0; e < r; ++e) skip |= (em[e] == m);
                    if (!skip) ins4(v, id, qq[j], m);
                }
            }
        }
        float vv = v[0]; int ii = id[0];
#pragma unroll
        for (int off = 16; off; off >>= 1) {
            float ov = __shfl_down_sync(FULL, vv, off);
            int   oi = __shfl_down_sync(FULL, ii, off);
            if (ov > vv || (ov == vv && oi < ii)) { vv = ov; ii = oi; }
        }
        const int bi = __shfl_sync(FULL, ii, 0);
        em[r] = bi;
        if (lane == 0) out[r] = bi;
        if (id[0] == bi) {   // owner lane pops (indices unique per lane)
#pragma unroll
            for (int q = 0; q < 3; ++q) { v[q] = v[q + 1]; id[q] = id[q + 1]; }
            v[3] = -INFINITY; id[3] = 0x7fffffff;
        }
    }
}

// ---------------- kNN pass 2: fp64 rescore + RANK-BASED top-10 (no serial shuffle chain) ----
// Candidates are distinct; total order (d desc, idx asc) => unique ranks 0..15.
// Lane i<16 writes out[rank_i] if rank_i < KNB. 16 independent broadcasts, fully pipelined.
template <int C>
__global__ void rerank(const float* __restrict__ x, const double* __restrict__ nrm,
                       const int* __restrict__ cand, int* __restrict__ idxout) {
    const unsigned FULL = 0xffffffffu;
    __shared__ float s_cent[8][C];
    const int warp = threadIdx.x >> 5, lane = threadIdx.x & 31;
    const int point = blockIdx.x * 8 + warp;          // global b*NPTS+n
    const int browbase = point & ~(NPTS - 1);
    const float* xb = x + (size_t)browbase * C;
    const int nloc = point - browbase;

    for (int c = lane; c < C; c += 32) s_cent[warp][c] = xb[(size_t)nloc * C + c];
    __syncwarp();

    double d = -INFINITY;
    int mi = 0x7fffffff;
    if (lane < KSEL) {
        mi = cand[(size_t)point * KSEL + lane];
        const float* row = xb + (size_t)mi * C;
        if (C % 4 == 0) {
            double a0 = 0.0, a1 = 0.0, a2 = 0.0, a3 = 0.0;
#pragma unroll
            for (int c = 0; c < C; c += 4) {
                float4 r = *(const float4*)&row[c];
                a0 += (double)s_cent[warp][c + 0] * (double)r.x;
                a1 += (double)s_cent[warp][c + 1] * (double)r.y;
                a2 += (double)s_cent[warp][c + 2] * (double)r.z;
                a3 += (double)s_cent[warp][c + 3] * (double)r.w;
            }
            d = 2.0 * ((a0 + a1) + (a2 + a3)) - nrm[point] - nrm[browbase + mi];
        } else {
            double dot = 0.0;
#pragma unroll
            for (int c = 0; c < C; ++c)
                dot += (double)s_cent[warp][c] * (double)row[c];
            d = 2.0 * dot - nrm[point] - nrm[browbase + mi];
        }
    }

    int rank = 0;
#pragma unroll
    for (int j = 0; j < KSEL; ++j) {
        double dj = __shfl_sync(FULL, d, j);
        int    mj = __shfl_sync(FULL, mi, j);
        rank += (dj > d || (dj == d && mj < mi)) ? 1 : 0;
    }
    if (lane < KSEL && rank < KNB)
        idxout[(size_t)point * KNB + rank] = mi;
}

// ---------------- weight prep: Wp = [A ; B - A] ----------------
__global__ void prep_w(const float* __restrict__ w, float* __restrict__ wp, int O, int C) {
    int i = blockIdx.x * 256 + threadIdx.x;
    if (i < O * C) {
        int o = i / C, c = i % C;
        float a = w[(size_t)o * 2 * C + c];
        wp[i] = a;
        wp[(size_t)O * C + i] = w[(size_t)o * 2 * C + C + c] - a;
    }
}

// ---------------- gather + reduce + BN + lrelu (fused transposed store for layer 4) ----------
template <int O>
__global__ void __launch_bounds__(256)
edge_reduce(const float* __restrict__ yz, const int* __restrict__ idx,
            const float* __restrict__ gg, const float* __restrict__ bb,
            const float* __restrict__ rm, const float* __restrict__ rv,
            float* __restrict__ xout, float* __restrict__ outT) {
    constexpr int PPB = 256 / O;
    const int pl = threadIdx.x / O;        // local point 0..PPB-1
    const int o  = threadIdx.x % O;
    const int bn = blockIdx.x * PPB + pl;  // global b*NPTS+n
    const int b = bn >> 11, n = bn & 2047;
    __shared__ int sj[PPB][KNB];
    if (o < KNB) sj[pl][o] = idx[(size_t)bn * KNB + o];
    __syncthreads();
    const double scale = (double)gg[o] / sqrt((double)rv[o] + 1e-5);
    const int twoO = 2 * O;
    const float z = yz[(size_t)bn * twoO + O + o];
    const int browbase = b << 11;
    float red;
    if (scale >= 0.0) {
        red = -INFINITY;
#pragma unroll
        for (int j = 0; j < KNB; ++j)
            red = fmaxf(red, yz[(size_t)(browbase + sj[pl][j]) * twoO + o]);
    } else {
        red = INFINITY;
#pragma unroll
        for (int j = 0; j < KNB; ++j)
            red = fminf(red, yz[(size_t)(browbase + sj[pl][j]) * twoO + o]);
    }
    double h = (((double)red + (double)z) - (double)rm[o]) * scale + (double)bb[o];
    float hf = (float)h;
    float r = hf >= 0.f ? hf : 0.2f * hf;
    xout[(size_t)bn * O + o] = r;
    if (outT) outT[((size_t)b * O + o) * NPTS + n] = r;
}

// ---------------- global max (two pass) ----------------
__global__ void gmax_partial(const float* __restrict__ x1, const float* __restrict__ x2,
                             const float* __restrict__ x3, const float* __restrict__ x4,
                             float* __restrict__ part) {
    const int b = blockIdx.x, chunk = blockIdx.y;
    const int c = threadIdx.x;  // 0..511
    const float* src; int O, off;
    if (c < 64)       { src = x1; O = 64;  off = c; }
    else if (c < 128) { src = x2; O = 64;  off = c - 64; }
    else if (c < 256) { src = x3; O = 128; off = c - 128; }
    else              { src = x4; O = 256; off = c - 256; }
    float m = -INFINITY;
    const int nbeg = chunk * 128;
    const float* p = src + ((size_t)b * NPTS + nbeg) * O + off;
    for (int n = 0; n < 128; ++n) m = fmaxf(m, p[(size_t)n * O]);
    part[((size_t)b * 16 + chunk) * 512 + c] = m;
}

__global__ void gmax_final(const float* __restrict__ part, float* __restrict__ gmax) {
    const int b = blockIdx.x, c = threadIdx.x;
    float m = -INFINITY;
    for (int ch = 0; ch < 16; ++ch)
        m = fmaxf(m, part[((size_t)b * 16 + ch) * 512 + c]);
    gmax[(size_t)b * 512 + c] = m;
}

// ---------------- final FC + BN + lrelu (fp64 accumulate) ----------------
__global__ void final_fc(const float* __restrict__ gmax, const float* __restrict__ lw,
                         const float* __restrict__ lb, const float* __restrict__ g5,
                         const float* __restrict__ b5, const float* __restrict__ rm5,
                         const float* __restrict__ rv5, float* __restrict__ out) {
    const int b = blockIdx.y;
    const int o = blockIdx.x * 256 + threadIdx.x;
    __shared__ float sg[512];
    for (int i = threadIdx.x; i < 512; i += 256) sg[i] = gmax[(size_t)b * 512 + i];
    __syncthreads();
    const float* wrow = lw + (size_t)o * 512;
    double acc = 0.0;
#pragma unroll 8
    for (int c = 0; c < 512; ++c) acc += (double)sg[c] * (double)wrow[c];
    acc += (double)lb[o];
    const double scale = (double)g5[o] / sqrt((double)rv5[o] + 1e-5);
    double h = (acc - (double)rm5[o]) * scale + (double)b5[o];
    float hf = (float)h;
    out[(size_t)b * 1024 + o] = hf >= 0.f ? hf : 0.2f * hf;
}

// ---------------- launch ----------------
extern "C" void kernel_launch(void* const* d_in, const int* in_sizes, int n_in,
                              void* d_out, int out_size) {
    const float* x    = (const float*)d_in[0];
    const float* w1   = (const float*)d_in[1];
    const float* g1   = (const float*)d_in[2];
    const float* b1   = (const float*)d_in[3];
    const float* rm1  = (const float*)d_in[4];
    const float* rv1  = (const float*)d_in[5];
    const float* w2   = (const float*)d_in[6];
    const float* g2   = (const float*)d_in[7];
    const float* b2   = (const float*)d_in[8];
    const float* rm2  = (const float*)d_in[9];
    const float* rv2  = (const float*)d_in[10];
    const float* w3   = (const float*)d_in[11];
    const float* g3   = (const float*)d_in[12];
    const float* b3   = (const float*)d_in[13];
    const float* rm3  = (const float*)d_in[14];
    const float* rv3  = (const float*)d_in[15];
    const float* w4   = (const float*)d_in[16];
    const float* g4   = (const float*)d_in[17];
    const float* b4   = (const float*)d_in[18];
    const float* rm4  = (const float*)d_in[19];
    const float* rv4  = (const float*)d_in[20];
    const float* lw   = (const float*)d_in[21];
    const float* lb   = (const float*)d_in[22];
    const float* g5   = (const float*)d_in[23];
    const float* b5   = (const float*)d_in[24];
    const float* rm5  = (const float*)d_in[25];
    const float* rv5  = (const float*)d_in[26];

    float *x1, *x2, *x3, *x4, *yz, *wp, *part, *gmax, *dist, *nrmf;
    int *idx, *cand;
    double* nrm;
    cudaGetSymbolAddress((void**)&x1, d_x1);
    cudaGetSymbolAddress((void**)&x2, d_x2);
    cudaGetSymbolAddress((void**)&x3, d_x3);
    cudaGetSymbolAddress((void**)&x4, d_x4);
    cudaGetSymbolAddress((void**)&yz, d_yz);
    cudaGetSymbolAddress((void**)&dist, d_dist);
    cudaGetSymbolAddress((void**)&idx, d_idxbuf);
    cudaGetSymbolAddress((void**)&cand, d_cand);
    cudaGetSymbolAddress((void**)&nrm, d_norm);
    cudaGetSymbolAddress((void**)&nrmf, d_normf);
    cudaGetSymbolAddress((void**)&wp, d_wp);
    cudaGetSymbolAddress((void**)&part, d_part);
    cudaGetSymbolAddress((void**)&gmax, d_gmax);

    float* out = (float*)d_out;
    float* x4T = out + B_ * 1024;

    const dim3 dist_grid(NPTS / 128, NPTS / 128, B_);
    const int nrm_blocks = (MTOT * 32 + 255) / 256;
    const int sel_blocks = MTOT / 8;
    const int rr_blocks = MTOT / 8;

    // layer 1: C=5 -> O=64   (rerank<5> at capture slot #4: A/B vs R16's 136us)
    compute_norms<5><<<nrm_blocks, 256>>>(x, nrm, nrmf);
    gemm128<5, true><<<dist_grid, 256>>>(x, nullptr, nrmf, dist, NPTS);
    select16<<<sel_blocks, 256>>>(dist, cand);
    rerank<5><<<rr_blocks, 256>>>(x, nrm, cand, idx);
    prep_w<<<(64 * 5 + 255) / 256, 256>>>(w1, wp, 64, 5);
    gemm128<5, false><<<dim3(1, MTOT / 128, 1), 256>>>(x, wp, nullptr, yz, 128);
    edge_reduce<64><<<MTOT / 4, 256>>>(yz, idx, g1, b1, rm1, rv1, x1, nullptr);

    // layer 2: C=64 -> O=64
    compute_norms<64><<<nrm_blocks, 256>>>(x1, nrm, nrmf);
    gemm128<64, true><<<dist_grid, 256>>>(x1, nullptr, nrmf, dist, NPTS);
    select16<<<sel_blocks, 256>>>(dist, cand);
    rerank<64><<<rr_blocks, 256>>>(x1, nrm, cand, idx);
    prep_w<<<(64 * 64 + 255) / 256, 256>>>(w2, wp, 64, 64);
    gemm128<64, false><<<dim3(1, MTOT / 128, 1), 256>>>(x1, wp, nullptr, yz, 128);
    edge_reduce<64><<<MTOT / 4, 256>>>(yz, idx, g2, b2, rm2, rv2, x2, nullptr);

    // layer 3: C=64 -> O=128
    compute_norms<64><<<nrm_blocks, 256>>>(x2, nrm, nrmf);
    gemm128<64, true><<<dist_grid, 256>>>(x2, nullptr, nrmf, dist, NPTS);
    select16<<<sel_blocks, 256>>>(dist, cand);
    rerank<64><<<rr_blocks, 256>>>(x2, nrm, cand, idx);
    prep_w<<<(128 * 64 + 255) / 256, 256>>>(w3, wp, 128, 64);
    gemm128<64, false><<<dim3(2, MTOT / 128, 1), 256>>>(x2, wp, nullptr, yz, 256);
    edge_reduce<128><<<MTOT / 2, 256>>>(yz, idx, g3, b3, rm3, rv3, x3, nullptr);

    // layer 4: C=128 -> O=256 (fused transposed output, R10-proven)
    compute_norms<128><<<nrm_blocks, 256>>>(x3, nrm, nrmf);
    gemm128<128, true><<<dist_grid, 256>>>(x3, nullptr, nrmf, dist, NPTS);
    select16<<<sel_blocks, 256>>>(dist, cand);
    rerank<128><<<rr_blocks, 256>>>(x3, nrm, cand, idx);
    prep_w<<<(256 * 128 + 255) / 256, 256>>>(w4, wp, 256, 128);
    gemm128<128, false><<<dim3(4, MTOT / 128, 1), 256>>>(x3, wp, nullptr, yz, 512);
    edge_reduce<256><<<MTOT, 256>>>(yz, idx, g4, b4, rm4, rv4, x4, x4T);

    // global max + final FC
    gmax_partial<<<dim3(B_, 16), 512>>>(x1, x2, x3, x4, part);
    gmax_final<<<B_, 512>>>(part, gmax);
    final_fc<<<dim3(4, B_), 256>>>(gmax, lw, lb, g5, b5, rm5, rv5, out);
}